// round 15
// baseline (speedup 1.0000x reference)
#include <cuda_runtime.h>
#include <cuda_fp16.h>
#include <cstdint>

// Matern-3/2 Gram via single-pass fp16 HMMA, fused epilogue.
// R15: R12 warp code exactly; CTA covers 64x128 via two Z tiles, all loads in
// ONE cp.async phase (X tile amortized, one barrier). Regs stay ~64.
// X[8192,64] f32, Z[4096,64] f32 -> out[8192,4096] f32.

#define SQRT3F   1.7320508075688772f
#define LOG2EF   1.4426950408889634f
constexpr int KD   = 64;
constexpr int BM   = 64;
constexpr int BN   = 64;
constexpr int NMAX = 8192;
constexpr int MMAX = 4096;

__device__ float g_rowsq[NMAX + MMAX];
__device__ __align__(16) __half g_xh[NMAX * KD];
__device__ __align__(16) __half g_zh[MMAX * KD];

__device__ __forceinline__ uint32_t smem_u32(const void* p) {
    uint32_t a;
    asm("{ .reg .u64 t; cvta.to.shared.u64 t, %1; cvt.u32.u64 %0, t; }"
        : "=r"(a) : "l"(p));
    return a;
}
#define SW128(o) ((o) ^ (((o) >> 3) & 0x70))

__device__ __forceinline__ void ldsm_x4(uint32_t r[4], uint32_t addr) {
    asm volatile("ldmatrix.sync.aligned.m8n8.x4.shared.b16 {%0,%1,%2,%3}, [%4];"
                 : "=r"(r[0]), "=r"(r[1]), "=r"(r[2]), "=r"(r[3])
                 : "r"(addr));
}
__device__ __forceinline__ void mma_f16(float c[4], const uint32_t a[4],
                                        uint32_t b0, uint32_t b1) {
    asm volatile(
        "mma.sync.aligned.m16n8k16.row.col.f32.f16.f16.f32 "
        "{%0,%1,%2,%3}, {%4,%5,%6,%7}, {%8,%9}, {%0,%1,%2,%3};"
        : "+f"(c[0]), "+f"(c[1]), "+f"(c[2]), "+f"(c[3])
        : "r"(a[0]), "r"(a[1]), "r"(a[2]), "r"(a[3]), "r"(b0), "r"(b1));
}
__device__ __forceinline__ void cp16(uint32_t dst, const void* src) {
    asm volatile("cp.async.cg.shared.global [%0], [%1], 16;"
                 :: "r"(dst), "l"((size_t)__cvta_generic_to_global(src)) : "memory");
}
#define CP_COMMIT() asm volatile("cp.async.commit_group;" ::: "memory")
template <int N> __device__ __forceinline__ void cp_wait() {
    asm volatile("cp.async.wait_group %0;" :: "n"(N) : "memory");
}
__device__ __forceinline__ float sqrt_approx(float x) {
    float r; asm("sqrt.approx.f32 %0, %1;" : "=f"(r) : "f"(x)); return r;
}
__device__ __forceinline__ float ex2_approx(float x) {
    float r; asm("ex2.approx.f32 %0, %1;" : "=f"(r) : "f"(x)); return r;
}

// ---------------- vectorized prologue: 16 lanes per row ----------------
__global__ __launch_bounds__(512) void prep_kernel(
    const float* __restrict__ X, const float* __restrict__ Z, int N, int M)
{
    int t   = blockIdx.x * blockDim.x + threadIdx.x;
    int row = t >> 4;
    int l16 = t & 15;
    if (row >= N + M) return;

    const float* rp;
    __half* hp;
    if (row < N) { rp = X + (size_t)row * KD;       hp = g_xh + (size_t)row * KD; }
    else         { rp = Z + (size_t)(row - N) * KD; hp = g_zh + (size_t)(row - N) * KD; }

    float4 v = ((const float4*)rp)[l16];
    __half2 h01(__float2half_rn(v.x), __float2half_rn(v.y));
    __half2 h23(__float2half_rn(v.z), __float2half_rn(v.w));
    uint2 u;
    u.x = *(uint32_t*)&h01;
    u.y = *(uint32_t*)&h23;
    ((uint2*)hp)[l16] = u;

    float s = v.x * v.x + v.y * v.y + v.z * v.z + v.w * v.w;
#pragma unroll
    for (int off = 8; off > 0; off >>= 1)
        s += __shfl_xor_sync(0xFFFFFFFFu, s, off);
    if (l16 == 0) g_rowsq[row] = s;
}

// ---------------- main HMMA kernel: 64x128 per CTA (2 Z tiles), 4 warps ----
constexpr int SM_XH = 0;                    // 64 rows x 128B
constexpr int SM_Z0 = 8192;                 // Z tile 0
constexpr int SM_Z1 = 16384;                // Z tile 1
constexpr int SM_Z2 = 24576;                // z2 norms: 2 x 256B
constexpr int SM_X2 = 24576 + 512;          // x2 norms: 256B
constexpr int SM_TOTAL = SM_X2 + 256;       // 25344

// fragment-position -> output-column permutation within a 32-col group
__device__ __forceinline__ int actual32(int f) {
    int j = f >> 3, q = (f >> 1) & 3, e = f & 1;
    return ((j >> 1) << 4) + (q << 2) + ((j & 1) << 1) + e;
}

__global__ __launch_bounds__(128, 8) void matern_hmma_kernel(
    const float* __restrict__ sigma, const float* __restrict__ lengthscale,
    float* __restrict__ out, int N, int M)
{
    __shared__ __align__(1024) char smem[SM_TOTAL];
    const uint32_t smem_base = smem_u32(smem);
    const int tid  = threadIdx.x;
    const int wid  = tid >> 5;
    const int lane = tid & 31;
    const int wrow = wid & 1;
    const int wcol = wid >> 1;
    const int q    = lane & 3;
    const int brow  = blockIdx.y * BM;
    const int bcol0 = blockIdx.x * (2 * BN);

    // ---- ONE async load phase: X tile + both Z tiles (row-permuted) + norms --
    {
        const uint4* xg = (const uint4*)g_xh + (size_t)brow * 8;
        const uint4* zg = (const uint4*)g_zh + (size_t)bcol0 * 8;
#pragma unroll
        for (int t = 0; t < 4; t++) {
            int li = tid + t * 128;           // 0..511
            int r  = li >> 3;                 // row 0..63
            int c  = li & 7;
            uint32_t so = SW128((uint32_t)(r * 128 + c * 16));
            cp16(smem_base + SM_XH + so, xg + (size_t)r * 8 + c);
            int zr = (r & 32) + actual32(r & 31);
            cp16(smem_base + SM_Z0 + so, zg + (size_t)zr * 8 + c);
            cp16(smem_base + SM_Z1 + so, zg + (size_t)(zr + BN) * 8 + c);
        }
        if (tid < 32)
            cp16(smem_base + SM_Z2 + tid * 16, &g_rowsq[N + bcol0 + tid * 4]);
        else if (tid < 48)
            cp16(smem_base + SM_X2 + (tid - 32) * 16,
                 &g_rowsq[brow + (tid - 32) * 4]);
        CP_COMMIT();
    }

    // ---- per-thread invariants (computed while loads fly) ----
    const uint32_t m    = (uint32_t)((lane & 7) * 16);
    const uint32_t a_kh = (uint32_t)((lane >> 4) * 16);
    const uint32_t b_kh = (uint32_t)(((lane >> 3) & 1) * 16);
    uint32_t a_base[2], b_off[2];
#pragma unroll
    for (int g = 0; g < 2; g++)
        a_base[g] = smem_base + SM_XH +
                    (uint32_t)((wrow * 32 + g * 16 + (lane & 15)) * 128);
#pragma unroll
    for (int h = 0; h < 2; h++)
        b_off[h] = (uint32_t)((wcol * 32 + h * 16 + (lane & 7) +
                               ((lane >> 4) << 3)) * 128);
    uint32_t ka[4], kb[4];
#pragma unroll
    for (int ks = 0; ks < 4; ks++) {
        ka[ks] = ((uint32_t)(ks * 32) + a_kh) ^ m;
        kb[ks] = ((uint32_t)(ks * 32) + b_kh) ^ m;
    }

    // epilogue constants
    const float sg   = sigma[0];
    const float s2   = sg * sg;
    const float kv   = SQRT3F / lengthscale[0];
    const float s2kv = s2 * kv;          // A = fma(d, s2kv, s2)
    const float nkv2 = -kv * LOG2EF;     // e = ex2(d * nkv2)

    cp_wait<0>();
    __syncthreads();

    const float* x2s = (const float*)(smem + SM_X2);

#pragma unroll
    for (int t = 0; t < 2; t++) {
        const uint32_t zb = smem_base + (t ? SM_Z1 : SM_Z0);
        const int bcol = bcol0 + t * BN;

        float acc[2][4][4];
#pragma unroll
        for (int g = 0; g < 2; g++)
#pragma unroll
            for (int j = 0; j < 4; j++)
#pragma unroll
                for (int e = 0; e < 4; e++) acc[g][j][e] = 0.f;

        // ---- mainloop: 4 k-steps, single fp16 pass (R12 per-warp code) ----
#pragma unroll
        for (int ks = 0; ks < 4; ks++) {
            uint32_t a[2][4], b[2][4];
#pragma unroll
            for (int g = 0; g < 2; g++)
                ldsm_x4(a[g], a_base[g] + ka[ks]);
#pragma unroll
            for (int h = 0; h < 2; h++)
                ldsm_x4(b[h], zb + b_off[h] + kb[ks]);
#pragma unroll
            for (int g = 0; g < 2; g++)
#pragma unroll
                for (int j = 0; j < 4; j++) {
                    const int hh = j >> 1, qq = (j & 1) * 2;
                    mma_f16(acc[g][j], a[g], b[hh][qq], b[hh][qq + 1]);
                }
        }

        // ---- scalar f32 Matern-3/2 epilogue, STG.128 ----
        float4 zc[2];
#pragma unroll
        for (int jj = 0; jj < 2; jj++)
            zc[jj] = *(const float4*)((const float*)(smem + SM_Z2) + t * 64 +
                                      wcol * 32 + jj * 16 + q * 4);

#pragma unroll
        for (int g = 0; g < 2; g++) {
#pragma unroll
            for (int sub = 0; sub < 2; sub++) {
                const int row = wrow * 32 + g * 16 + (lane >> 2) + sub * 8;
                const float x2 = x2s[row];
                float* rowptr = out + (size_t)(brow + row) * (size_t)M + bcol;
#pragma unroll
                for (int jj = 0; jj < 2; jj++) {
                    float4 o;
#pragma unroll
                    for (int e = 0; e < 4; e++) {
                        float dot = acc[g][2 * jj + (e >> 1)][sub * 2 + (e & 1)];
                        float z2  = ((const float*)&zc[jj])[e];
                        float sq  = __fmaf_rn(-2.0f, dot, x2 + z2);
                        float d   = sqrt_approx(sq);
                        float A   = __fmaf_rn(d, s2kv, s2);
                        float ee  = ex2_approx(d * nkv2);
                        ((float*)&o)[e] = A * ee;
                    }
                    *(float4*)(rowptr + wcol * 32 + jj * 16 + q * 4) = o;
                }
            }
        }
    }
}

extern "C" void kernel_launch(void* const* d_in, const int* in_sizes, int n_in,
                              void* d_out, int out_size) {
    const float* X   = (const float*)d_in[0];
    const float* Z   = (const float*)d_in[1];
    const float* sig = (const float*)d_in[2];
    const float* len = (const float*)d_in[3];
    float* out = (float*)d_out;

    int N = in_sizes[0] / KD;   // 8192
    int M = in_sizes[1] / KD;   // 4096

    int totalthreads = (N + M) * 16;                // 16 lanes per row
    prep_kernel<<<(totalthreads + 511) / 512, 512>>>(X, Z, N, M);

    dim3 grid(M / (2 * BN), N / BM);                // (32, 128) = 4096 CTAs
    matern_hmma_kernel<<<grid, 128>>>(sig, len, out, N, M);
}

// round 16
// speedup vs baseline: 1.5630x; 1.5630x over previous
#include <cuda_runtime.h>
#include <cuda_fp16.h>
#include <cstdint>

// Matern-3/2 Gram via single-pass fp16 HMMA, fused epilogue.
// R16: R12 exactly, with the cp.async load-phase address arithmetic
// strength-reduced (constant swizzle mask across iterations; +2048B steps).
// X[8192,64] f32, Z[4096,64] f32 -> out[8192,4096] f32.

#define SQRT3F   1.7320508075688772f
#define LOG2EF   1.4426950408889634f
constexpr int KD   = 64;
constexpr int BM   = 64;
constexpr int BN   = 64;
constexpr int NMAX = 8192;
constexpr int MMAX = 4096;

__device__ float g_rowsq[NMAX + MMAX];
__device__ __align__(16) __half g_xh[NMAX * KD];
__device__ __align__(16) __half g_zh[MMAX * KD];

__device__ __forceinline__ uint32_t smem_u32(const void* p) {
    uint32_t a;
    asm("{ .reg .u64 t; cvta.to.shared.u64 t, %1; cvt.u32.u64 %0, t; }"
        : "=r"(a) : "l"(p));
    return a;
}
#define SW128(o) ((o) ^ (((o) >> 3) & 0x70))

__device__ __forceinline__ void ldsm_x4(uint32_t r[4], uint32_t addr) {
    asm volatile("ldmatrix.sync.aligned.m8n8.x4.shared.b16 {%0,%1,%2,%3}, [%4];"
                 : "=r"(r[0]), "=r"(r[1]), "=r"(r[2]), "=r"(r[3])
                 : "r"(addr));
}
__device__ __forceinline__ void mma_f16(float c[4], const uint32_t a[4],
                                        uint32_t b0, uint32_t b1) {
    asm volatile(
        "mma.sync.aligned.m16n8k16.row.col.f32.f16.f16.f32 "
        "{%0,%1,%2,%3}, {%4,%5,%6,%7}, {%8,%9}, {%0,%1,%2,%3};"
        : "+f"(c[0]), "+f"(c[1]), "+f"(c[2]), "+f"(c[3])
        : "r"(a[0]), "r"(a[1]), "r"(a[2]), "r"(a[3]), "r"(b0), "r"(b1));
}
__device__ __forceinline__ void cp16(uint32_t dst, const void* src) {
    asm volatile("cp.async.cg.shared.global [%0], [%1], 16;"
                 :: "r"(dst), "l"((size_t)__cvta_generic_to_global(src)) : "memory");
}
#define CP_COMMIT() asm volatile("cp.async.commit_group;" ::: "memory")
template <int N> __device__ __forceinline__ void cp_wait() {
    asm volatile("cp.async.wait_group %0;" :: "n"(N) : "memory");
}
__device__ __forceinline__ float sqrt_approx(float x) {
    float r; asm("sqrt.approx.f32 %0, %1;" : "=f"(r) : "f"(x)); return r;
}
__device__ __forceinline__ float ex2_approx(float x) {
    float r; asm("ex2.approx.f32 %0, %1;" : "=f"(r) : "f"(x)); return r;
}

// ---------------- vectorized prologue: 16 lanes per row ----------------
__global__ __launch_bounds__(512) void prep_kernel(
    const float* __restrict__ X, const float* __restrict__ Z, int N, int M)
{
    int t   = blockIdx.x * blockDim.x + threadIdx.x;
    int row = t >> 4;
    int l16 = t & 15;
    if (row >= N + M) return;

    const float* rp;
    __half* hp;
    if (row < N) { rp = X + (size_t)row * KD;       hp = g_xh + (size_t)row * KD; }
    else         { rp = Z + (size_t)(row - N) * KD; hp = g_zh + (size_t)(row - N) * KD; }

    float4 v = ((const float4*)rp)[l16];
    __half2 h01(__float2half_rn(v.x), __float2half_rn(v.y));
    __half2 h23(__float2half_rn(v.z), __float2half_rn(v.w));
    uint2 u;
    u.x = *(uint32_t*)&h01;
    u.y = *(uint32_t*)&h23;
    ((uint2*)hp)[l16] = u;

    float s = v.x * v.x + v.y * v.y + v.z * v.z + v.w * v.w;
#pragma unroll
    for (int off = 8; off > 0; off >>= 1)
        s += __shfl_xor_sync(0xFFFFFFFFu, s, off);
    if (l16 == 0) g_rowsq[row] = s;
}

// ---------------- main HMMA kernel: 64x64 tile, 4 warps (2x2) ----------------
constexpr int SM_XH = 0;
constexpr int SM_ZH = 8192;
constexpr int SM_Z2 = 16384;           // 256B z2 block
constexpr int SM_X2 = 16384 + 256;     // 256B x2 block
constexpr int SM_TOTAL = SM_X2 + 256;  // 16896

// fragment-position -> output-column permutation within a 32-col group
__device__ __forceinline__ int actual32(int f) {
    int j = f >> 3, q = (f >> 1) & 3, e = f & 1;
    return ((j >> 1) << 4) + (q << 2) + ((j & 1) << 1) + e;
}

__global__ __launch_bounds__(128, 8) void matern_hmma_kernel(
    const float* __restrict__ sigma, const float* __restrict__ lengthscale,
    float* __restrict__ out, int N, int M)
{
    __shared__ __align__(1024) char smem[SM_TOTAL];
    const uint32_t smem_base = smem_u32(smem);
    const int tid  = threadIdx.x;
    const int wid  = tid >> 5;
    const int lane = tid & 31;
    const int wrow = wid & 1;
    const int wcol = wid >> 1;
    const int q    = lane & 3;
    const int brow = blockIdx.y * BM;
    const int bcol = blockIdx.x * BN;

    // ---- async-load X (natural) and Z (row-permuted) f16 tiles + norms ----
    // Strength-reduced: rows step by 16 per iteration, so the SW128 mask
    // ((r&7)*16) is iteration-invariant and the swizzled dst advances +2048B;
    // sources advance by 16 rows (= 128 uint4). Z row permutation takes only
    // two values (zr0, zr1), repeating +32 for the second pair.
    {
        const int r0 = tid >> 3;            // 0..15
        const int c  = tid & 7;
        const uint32_t so0 = SW128((uint32_t)(r0 * 128 + c * 16));
        const uint4* xsrc  = (const uint4*)g_xh + (size_t)(brow + r0) * 8 + c;
        const int zr0 = actual32(r0);       // r0 in [0,16)
        const int zr1 = actual32(r0 + 16);  // in [0,32)
        const uint4* zsrc0 = (const uint4*)g_zh + (size_t)(bcol + zr0) * 8 + c;
        const uint4* zsrc1 = (const uint4*)g_zh + (size_t)(bcol + zr1) * 8 + c;

        cp16(smem_base + SM_XH + so0,        xsrc);
        cp16(smem_base + SM_XH + so0 + 2048, xsrc + 128);
        cp16(smem_base + SM_XH + so0 + 4096, xsrc + 256);
        cp16(smem_base + SM_XH + so0 + 6144, xsrc + 384);

        cp16(smem_base + SM_ZH + so0,        zsrc0);         // rows r0      -> zr0
        cp16(smem_base + SM_ZH + so0 + 2048, zsrc1);         // rows r0+16   -> zr1
        cp16(smem_base + SM_ZH + so0 + 4096, zsrc0 + 256);   // rows r0+32   -> zr0+32
        cp16(smem_base + SM_ZH + so0 + 6144, zsrc1 + 256);   // rows r0+48   -> zr1+32

        if (tid < 16)
            cp16(smem_base + SM_Z2 + tid * 16, &g_rowsq[N + bcol + tid * 4]);
        else if (tid < 32)
            cp16(smem_base + SM_X2 + (tid - 16) * 16,
                 &g_rowsq[brow + (tid - 16) * 4]);
        CP_COMMIT();
    }

    // ---- per-thread invariants (computed while loads fly) ----
    const uint32_t m    = (uint32_t)((lane & 7) * 16);
    const uint32_t a_kh = (uint32_t)((lane >> 4) * 16);
    const uint32_t b_kh = (uint32_t)(((lane >> 3) & 1) * 16);
    uint32_t a_base[2], b_base[2];
#pragma unroll
    for (int g = 0; g < 2; g++)
        a_base[g] = smem_base + SM_XH +
                    (uint32_t)((wrow * 32 + g * 16 + (lane & 15)) * 128);
#pragma unroll
    for (int h = 0; h < 2; h++)
        b_base[h] = smem_base + SM_ZH +
                    (uint32_t)((wcol * 32 + h * 16 + (lane & 7) +
                                ((lane >> 4) << 3)) * 128);
    uint32_t ka[4], kb[4];
#pragma unroll
    for (int ks = 0; ks < 4; ks++) {
        ka[ks] = ((uint32_t)(ks * 32) + a_kh) ^ m;
        kb[ks] = ((uint32_t)(ks * 32) + b_kh) ^ m;
    }

    // epilogue constants
    const float sg   = sigma[0];
    const float s2   = sg * sg;
    const float kv   = SQRT3F / lengthscale[0];
    const float s2kv = s2 * kv;          // A = fma(d, s2kv, s2)
    const float nkv2 = -kv * LOG2EF;     // e = ex2(d * nkv2)

    float acc[2][4][4];
#pragma unroll
    for (int g = 0; g < 2; g++)
#pragma unroll
        for (int j = 0; j < 4; j++)
#pragma unroll
            for (int e = 0; e < 4; e++) acc[g][j][e] = 0.f;

    cp_wait<0>();
    __syncthreads();

    // ---- mainloop: 4 k-steps, single fp16 pass ----
#pragma unroll
    for (int ks = 0; ks < 4; ks++) {
        uint32_t a[2][4], b[2][4];
#pragma unroll
        for (int g = 0; g < 2; g++)
            ldsm_x4(a[g], a_base[g] + ka[ks]);
#pragma unroll
        for (int h = 0; h < 2; h++)
            ldsm_x4(b[h], b_base[h] + kb[ks]);
#pragma unroll
        for (int g = 0; g < 2; g++)
#pragma unroll
            for (int j = 0; j < 4; j++) {
                const int hh = j >> 1, qq = (j & 1) * 2;
                mma_f16(acc[g][j], a[g], b[hh][qq], b[hh][qq + 1]);
            }
    }

    // ---- scalar f32 Matern-3/2 epilogue, STG.128 ----
    float4 zc[2];
#pragma unroll
    for (int jj = 0; jj < 2; jj++)
        zc[jj] = *(const float4*)((const float*)(smem + SM_Z2) +
                                  wcol * 32 + jj * 16 + q * 4);
    const float* x2s = (const float*)(smem + SM_X2);

#pragma unroll
    for (int g = 0; g < 2; g++) {
#pragma unroll
        for (int sub = 0; sub < 2; sub++) {
            const int row = wrow * 32 + g * 16 + (lane >> 2) + sub * 8;
            const float x2 = x2s[row];
            float* rowptr = out + (size_t)(brow + row) * (size_t)M + bcol;
#pragma unroll
            for (int jj = 0; jj < 2; jj++) {
                float4 o;
#pragma unroll
                for (int e = 0; e < 4; e++) {
                    float dot = acc[g][2 * jj + (e >> 1)][sub * 2 + (e & 1)];
                    float z2  = ((const float*)&zc[jj])[e];
                    float sq  = __fmaf_rn(-2.0f, dot, x2 + z2);
                    float d   = sqrt_approx(sq);
                    float A   = __fmaf_rn(d, s2kv, s2);     // s2*(1+kv*d)
                    float ee  = ex2_approx(d * nkv2);       // exp(-kv*d)
                    ((float*)&o)[e] = A * ee;
                }
                *(float4*)(rowptr + wcol * 32 + jj * 16 + q * 4) = o;
            }
        }
    }
}

extern "C" void kernel_launch(void* const* d_in, const int* in_sizes, int n_in,
                              void* d_out, int out_size) {
    const float* X   = (const float*)d_in[0];
    const float* Z   = (const float*)d_in[1];
    const float* sig = (const float*)d_in[2];
    const float* len = (const float*)d_in[3];
    float* out = (float*)d_out;

    int N = in_sizes[0] / KD;   // 8192
    int M = in_sizes[1] / KD;   // 4096

    int totalthreads = (N + M) * 16;                // 16 lanes per row
    prep_kernel<<<(totalthreads + 511) / 512, 512>>>(X, Z, N, M);

    dim3 grid(M / BN, N / BM);                      // 8192 CTAs
    matern_hmma_kernel<<<grid, 128>>>(sig, len, out, N, M);
}